// round 8
// baseline (speedup 1.0000x reference)
#include <cuda_runtime.h>
#include <cuda_fp16.h>
#include <cstdint>

#define MM 8192
#define KK 4096
#define NN 4096

// GEMM tiling (fp16 mainloop)
#define BM 256
#define BN 128
#define BK 128            // K elems per stage (256 bytes of fp16)
#define NST 2
#define NCHUNK (KK / BK)  // 32
#define RS 272            // smem row stride bytes (256B data + 16B pad)

#define A_STG (BM * RS)           // 69632
#define B_STG (BN * RS)           // 34816
#define STG (A_STG + B_STG)       // 104448
#define SMEM_REQ (NST * STG)      // 208896

// Scratch (device globals — no allocation allowed)
__device__ __half g_qA[(size_t)MM * KK];   // [M][K] fp16 (integer values)
__device__ __half g_qBT[(size_t)NN * KK];  // [N][K] fp16 (B transposed)
__device__ float g_lsc[MM];
__device__ float g_rsc[NN];
__device__ float g_pmax[32 * NN];

// ---------------------------------------------------------------------------
// Kernel 1: per-row absmax + quantize of lhs -> fp16 integers
// ---------------------------------------------------------------------------
__global__ __launch_bounds__(256) void quant_lhs_kernel(const float* __restrict__ lhs) {
    int row = blockIdx.x;
    int t = threadIdx.x;
    const float4* src = (const float4*)(lhs + (size_t)row * KK);
    float4 v[4];
    float m = 0.0f;
#pragma unroll
    for (int i = 0; i < 4; i++) {
        v[i] = src[i * 256 + t];
        m = fmaxf(m, fmaxf(fmaxf(fabsf(v[i].x), fabsf(v[i].y)),
                           fmaxf(fabsf(v[i].z), fabsf(v[i].w))));
    }
#pragma unroll
    for (int o = 16; o > 0; o >>= 1) m = fmaxf(m, __shfl_xor_sync(0xffffffffu, m, o));
    __shared__ float red[8];
    if ((t & 31) == 0) red[t >> 5] = m;
    __syncthreads();
    m = red[0];
#pragma unroll
    for (int i = 1; i < 8; i++) m = fmaxf(m, red[i]);

    float scale = m / 127.0f;
    if (scale == 0.0f) scale = 1.0f;
    if (t == 0) g_lsc[row] = scale;

    __half2* qdst = (__half2*)(g_qA + (size_t)row * KK);
#pragma unroll
    for (int i = 0; i < 4; i++) {
        float r0 = fminf(fmaxf(rintf(v[i].x / scale), -127.0f), 127.0f);
        float r1 = fminf(fmaxf(rintf(v[i].y / scale), -127.0f), 127.0f);
        float r2 = fminf(fmaxf(rintf(v[i].z / scale), -127.0f), 127.0f);
        float r3 = fminf(fmaxf(rintf(v[i].w / scale), -127.0f), 127.0f);
        qdst[(i * 256 + t) * 2 + 0] = __floats2half2_rn(r0, r1);
        qdst[(i * 256 + t) * 2 + 1] = __floats2half2_rn(r2, r3);
    }
}

// ---------------------------------------------------------------------------
// Kernel 2a/2b: per-column absmax of rhs
// ---------------------------------------------------------------------------
__global__ __launch_bounds__(256) void rhs_pmax_kernel(const float* __restrict__ rhs) {
    int n = blockIdx.x * 256 + threadIdx.x;
    int k0 = blockIdx.y * 128;
    const float* p = rhs + (size_t)k0 * NN + n;
    float m = 0.0f;
#pragma unroll 8
    for (int k = 0; k < 128; k++) m = fmaxf(m, fabsf(p[(size_t)k * NN]));
    g_pmax[blockIdx.y * NN + n] = m;
}

__global__ __launch_bounds__(256) void rhs_scale_kernel() {
    int n = blockIdx.x * 256 + threadIdx.x;
    float m = 0.0f;
#pragma unroll
    for (int i = 0; i < 32; i++) m = fmaxf(m, g_pmax[i * NN + n]);
    float s = m / 127.0f;
    if (s == 0.0f) s = 1.0f;
    g_rsc[n] = s;
}

// ---------------------------------------------------------------------------
// Kernel 3: quantize rhs + transpose into [N][K] fp16
// ---------------------------------------------------------------------------
__global__ __launch_bounds__(256) void quant_rhs_kernel(const float* __restrict__ rhs) {
    __shared__ __half tile[64][68];
    int k0 = blockIdx.y * 64, n0 = blockIdx.x * 64;
    int t = threadIdx.x;
    int nl = t & 63;
    int kl0 = t >> 6;
    float s = g_rsc[n0 + nl];
#pragma unroll
    for (int i = 0; i < 16; i++) {
        int kl = kl0 + i * 4;
        float v = rhs[(size_t)(k0 + kl) * NN + n0 + nl];
        float r = fminf(fmaxf(rintf(v / s), -127.0f), 127.0f);
        tile[kl][nl] = __float2half_rn(r);
    }
    __syncthreads();
    int k4 = t & 15;
    int nl2 = t >> 4;
#pragma unroll
    for (int i = 0; i < 4; i++) {
        int nn = nl2 + i * 16;
        __half2 p0 = __halves2half2(tile[k4 * 4 + 0][nn], tile[k4 * 4 + 1][nn]);
        __half2 p1 = __halves2half2(tile[k4 * 4 + 2][nn], tile[k4 * 4 + 3][nn]);
        uint2 pk;
        pk.x = *(uint32_t*)&p0;
        pk.y = *(uint32_t*)&p1;
        *(uint2*)&g_qBT[(size_t)(n0 + nn) * KK + k0 + k4 * 4] = pk;
    }
}

// ---------------------------------------------------------------------------
// Kernel 4: pipelined fp16 GEMM with ldmatrix fragment loads
// Block 256x128, 16 warps (4m x 4n), warp tile 64x32, BK=128 double-buffered
// (32 barriers total instead of 64 -> amortized sync bubbles).
// ---------------------------------------------------------------------------
__device__ __forceinline__ void mma_f16(float& c0, float& c1, float& c2, float& c3,
                                        uint32_t a0, uint32_t a1, uint32_t a2, uint32_t a3,
                                        uint32_t b0, uint32_t b1) {
    asm volatile(
        "mma.sync.aligned.m16n8k16.row.col.f32.f16.f16.f32 "
        "{%0,%1,%2,%3}, {%4,%5,%6,%7}, {%8,%9}, {%0,%1,%2,%3};\n"
        : "+f"(c0), "+f"(c1), "+f"(c2), "+f"(c3)
        : "r"(a0), "r"(a1), "r"(a2), "r"(a3), "r"(b0), "r"(b1));
}

__device__ __forceinline__ void ldsm4(uint32_t& r0, uint32_t& r1, uint32_t& r2, uint32_t& r3,
                                      uint32_t addr) {
    asm volatile("ldmatrix.sync.aligned.m8n8.x4.shared.b16 {%0,%1,%2,%3}, [%4];"
                 : "=r"(r0), "=r"(r1), "=r"(r2), "=r"(r3) : "r"(addr));
}

__device__ __forceinline__ void cp16(uint32_t smem, const void* g) {
    asm volatile("cp.async.cg.shared.global [%0], [%1], 16;" :: "r"(smem), "l"(g));
}

__global__ void __launch_bounds__(512, 1)
gemm_f16_kernel(float* __restrict__ out) {
    extern __shared__ signed char sm[];
    uint32_t smb = (uint32_t)__cvta_generic_to_shared(sm);

    int tid = threadIdx.x;
    int warp = tid >> 5, lane = tid & 31;
    int wm = (warp & 3) * 64;    // warp m offset
    int wn = (warp >> 2) * 32;   // warp n offset
    int bm = blockIdx.y * BM, bn = blockIdx.x * BN;
    int grp = lane >> 2, tq = lane & 3;

    // cp.async mapping: rows of 256B = 16 chunks. A: 8 chunks/thread, B: 4.
    const __half* gA[8];
    uint32_t sA[8];
#pragma unroll
    for (int p = 0; p < 8; p++) {
        int i = p * 512 + tid;
        int r = i >> 4, s = i & 15;
        gA[p] = g_qA + (size_t)(bm + r) * KK + s * 8;
        sA[p] = smb + r * RS + s * 16;
    }
    const __half* gB[4];
    uint32_t sB[4];
#pragma unroll
    for (int p = 0; p < 4; p++) {
        int i = p * 512 + tid;
        int r = i >> 4, s = i & 15;
        gB[p] = g_qBT + (size_t)(bn + r) * KK + s * 8;
        sB[p] = smb + A_STG + r * RS + s * 16;
    }

    // ldmatrix per-lane base addresses
    uint32_t aLd = smb + (wm + (lane & 15)) * RS + (lane >> 4) * 16;
    uint32_t bLd = smb + A_STG +
                   (wn + ((lane >> 4) & 1) * 8 + (lane & 7)) * RS + ((lane >> 3) & 1) * 16;

    float acc[4][4][4];
#pragma unroll
    for (int mi = 0; mi < 4; mi++)
#pragma unroll
        for (int ni = 0; ni < 4; ni++)
#pragma unroll
            for (int r = 0; r < 4; r++) acc[mi][ni][r] = 0.0f;

    // Prologue: stage 0
#pragma unroll
    for (int p = 0; p < 8; p++) cp16(sA[p], gA[p]);
#pragma unroll
    for (int p = 0; p < 4; p++) cp16(sB[p], gB[p]);
    asm volatile("cp.async.commit_group;");

    int stage = 0;
    for (int kt = 0; kt < NCHUNK; kt++) {
        asm volatile("cp.async.wait_group 0;");
        __syncthreads();

        if (kt + 1 < NCHUNK) {
            int st = stage ^ 1;
            int ko = (kt + 1) * BK;
#pragma unroll
            for (int p = 0; p < 8; p++) cp16(sA[p] + st * STG, gA[p] + ko);
#pragma unroll
            for (int p = 0; p < 4; p++) cp16(sB[p] + st * STG, gB[p] + ko);
            asm volatile("cp.async.commit_group;");
        }

        uint32_t stoff = stage * STG;
#pragma unroll
        for (int ks = 0; ks < 8; ks++) {   // eight K=16 steps per 128-elem chunk
            uint32_t a[4][4], b[4][2];
#pragma unroll
            for (int mi = 0; mi < 4; mi++)
                ldsm4(a[mi][0], a[mi][1], a[mi][2], a[mi][3],
                      aLd + stoff + mi * 16 * RS + ks * 32);
#pragma unroll
            for (int np = 0; np < 2; np++)
                ldsm4(b[2 * np][0], b[2 * np][1], b[2 * np + 1][0], b[2 * np + 1][1],
                      bLd + stoff + np * 16 * RS + ks * 32);
#pragma unroll
            for (int mi = 0; mi < 4; mi++)
#pragma unroll
                for (int ni = 0; ni < 4; ni++)
                    mma_f16(acc[mi][ni][0], acc[mi][ni][1], acc[mi][ni][2], acc[mi][ni][3],
                            a[mi][0], a[mi][1], a[mi][2], a[mi][3], b[ni][0], b[ni][1]);
        }
        stage ^= 1;
    }

    // Epilogue: dequant + store
#pragma unroll
    for (int mi = 0; mi < 4; mi++) {
        int gm0 = bm + wm + mi * 16 + grp;
        float s0 = g_lsc[gm0];
        float s1 = g_lsc[gm0 + 8];
#pragma unroll
        for (int ni = 0; ni < 4; ni++) {
            int gn = bn + wn + ni * 8 + tq * 2;
            float r0 = g_rsc[gn];
            float r1 = g_rsc[gn + 1];
            float2 o0, o1;
            o0.x = acc[mi][ni][0] * s0 * r0;
            o0.y = acc[mi][ni][1] * s0 * r1;
            o1.x = acc[mi][ni][2] * s1 * r0;
            o1.y = acc[mi][ni][3] * s1 * r1;
            *(float2*)(out + (size_t)gm0 * NN + gn) = o0;
            *(float2*)(out + (size_t)(gm0 + 8) * NN + gn) = o1;
        }
    }
}

// ---------------------------------------------------------------------------
extern "C" void kernel_launch(void* const* d_in, const int* in_sizes, int n_in,
                              void* d_out, int out_size) {
    const float* lhs = (const float*)d_in[0];
    const float* rhs = (const float*)d_in[1];
    if (n_in >= 2 && in_sizes[0] == KK * NN && in_sizes[1] == MM * KK) {
        const float* t = lhs; lhs = rhs; rhs = t;
    }
    float* out = (float*)d_out;

    cudaFuncSetAttribute(gemm_f16_kernel, cudaFuncAttributeMaxDynamicSharedMemorySize, SMEM_REQ);

    quant_lhs_kernel<<<MM, 256>>>(lhs);
    rhs_pmax_kernel<<<dim3(NN / 256, 32), 256>>>(rhs);
    rhs_scale_kernel<<<NN / 256, 256>>>();
    quant_rhs_kernel<<<dim3(NN / 64, KK / 64), 256>>>(rhs);
    gemm_f16_kernel<<<dim3(NN / BN, MM / BM), 512, SMEM_REQ>>>(out);
}

// round 9
// speedup vs baseline: 1.0477x; 1.0477x over previous
#include <cuda_runtime.h>
#include <cuda_fp16.h>
#include <cstdint>

#define MM 8192
#define KK 4096
#define NN 4096

// GEMM tiling (fp16 mainloop) — exact R5 configuration (best: 790.6us)
#define BM 256
#define BN 128
#define BK 64             // K elems per stage (128 bytes of fp16)
#define NST 4
#define NCHUNK (KK / BK)  // 64
#define RS 144            // smem row stride bytes (128B data + 16B pad)

#define A_STG (BM * RS)           // 36864
#define B_STG (BN * RS)           // 18432
#define STG (A_STG + B_STG)       // 55296
#define SMEM_REQ (NST * STG)      // 221184

// Scratch (device globals — no allocation allowed)
__device__ __half g_qA[(size_t)MM * KK];   // [M][K] fp16 (integer values)
__device__ __half g_qBT[(size_t)NN * KK];  // [N][K] fp16 (B transposed)
__device__ float g_lsc[MM];
__device__ float g_rsc[NN];
__device__ float g_pmax[32 * NN];

__device__ __forceinline__ float qclip(float v, float s) {
    return fminf(fmaxf(rintf(v / s), -127.0f), 127.0f);
}

// ---------------------------------------------------------------------------
// Kernel 1: per-row absmax + quantize of lhs -> fp16 integers (16B stores)
// ---------------------------------------------------------------------------
__global__ __launch_bounds__(256) void quant_lhs_kernel(const float* __restrict__ lhs) {
    int row = blockIdx.x;
    int t = threadIdx.x;
    const float4* src = (const float4*)(lhs + (size_t)row * KK);
    // thread handles 2 groups of 8 consecutive floats (2x float4 each)
    float4 v[4];
    v[0] = src[2 * t];
    v[1] = src[2 * t + 1];
    v[2] = src[512 + 2 * t];
    v[3] = src[512 + 2 * t + 1];
    float m = 0.0f;
#pragma unroll
    for (int i = 0; i < 4; i++)
        m = fmaxf(m, fmaxf(fmaxf(fabsf(v[i].x), fabsf(v[i].y)),
                           fmaxf(fabsf(v[i].z), fabsf(v[i].w))));
#pragma unroll
    for (int o = 16; o > 0; o >>= 1) m = fmaxf(m, __shfl_xor_sync(0xffffffffu, m, o));
    __shared__ float red[8];
    if ((t & 31) == 0) red[t >> 5] = m;
    __syncthreads();
    m = red[0];
#pragma unroll
    for (int i = 1; i < 8; i++) m = fmaxf(m, red[i]);

    float scale = m / 127.0f;
    if (scale == 0.0f) scale = 1.0f;
    if (t == 0) g_lsc[row] = scale;

    uint4* qdst = (uint4*)(g_qA + (size_t)row * KK);
#pragma unroll
    for (int g = 0; g < 2; g++) {
        float4 a = v[2 * g], b = v[2 * g + 1];
        __half2 h0 = __floats2half2_rn(qclip(a.x, scale), qclip(a.y, scale));
        __half2 h1 = __floats2half2_rn(qclip(a.z, scale), qclip(a.w, scale));
        __half2 h2 = __floats2half2_rn(qclip(b.x, scale), qclip(b.y, scale));
        __half2 h3 = __floats2half2_rn(qclip(b.z, scale), qclip(b.w, scale));
        uint4 u;
        u.x = *(uint32_t*)&h0; u.y = *(uint32_t*)&h1;
        u.z = *(uint32_t*)&h2; u.w = *(uint32_t*)&h3;
        qdst[g * 256 + t] = u;
    }
}

// ---------------------------------------------------------------------------
// Kernel 2a/2b: per-column absmax of rhs (float4 columns)
// ---------------------------------------------------------------------------
__global__ __launch_bounds__(256) void rhs_pmax_kernel(const float* __restrict__ rhs) {
    int n4 = blockIdx.x * 256 + threadIdx.x;   // float4 index over N (0..1023)
    int k0 = blockIdx.y * 128;
    const float4* p = (const float4*)rhs + (size_t)k0 * (NN / 4) + n4;
    float4 m = make_float4(0.f, 0.f, 0.f, 0.f);
#pragma unroll 8
    for (int k = 0; k < 128; k++) {
        float4 v = p[(size_t)k * (NN / 4)];
        m.x = fmaxf(m.x, fabsf(v.x));
        m.y = fmaxf(m.y, fabsf(v.y));
        m.z = fmaxf(m.z, fabsf(v.z));
        m.w = fmaxf(m.w, fabsf(v.w));
    }
    ((float4*)g_pmax)[blockIdx.y * (NN / 4) + n4] = m;
}

__global__ __launch_bounds__(256) void rhs_scale_kernel() {
    int n4 = blockIdx.x * 256 + threadIdx.x;
    float4 m = make_float4(0.f, 0.f, 0.f, 0.f);
#pragma unroll
    for (int i = 0; i < 32; i++) {
        float4 v = ((const float4*)g_pmax)[i * (NN / 4) + n4];
        m.x = fmaxf(m.x, v.x); m.y = fmaxf(m.y, v.y);
        m.z = fmaxf(m.z, v.z); m.w = fmaxf(m.w, v.w);
    }
    float4 s;
    s.x = m.x / 127.0f; if (s.x == 0.0f) s.x = 1.0f;
    s.y = m.y / 127.0f; if (s.y == 0.0f) s.y = 1.0f;
    s.z = m.z / 127.0f; if (s.z == 0.0f) s.z = 1.0f;
    s.w = m.w / 127.0f; if (s.w == 0.0f) s.w = 1.0f;
    ((float4*)g_rsc)[n4] = s;
}

// ---------------------------------------------------------------------------
// Kernel 3: quantize rhs + transpose into [N][K] fp16
// float4 loads, pre-transposed smem tile, uint4 smem reads + global stores.
// ---------------------------------------------------------------------------
__global__ __launch_bounds__(256) void quant_rhs_kernel(const float* __restrict__ rhs) {
    __shared__ __half tileT[64][72];   // [n][k], 144B row stride (16B aligned)
    int k0 = blockIdx.y * 64, n0 = blockIdx.x * 64;
    int t = threadIdx.x;
    int nl4 = t & 15;   // float4 column group (covers n = nl4*4 .. +3)
    int kl = t >> 4;    // 0..15
    float4 s4 = ((const float4*)g_rsc)[(n0 >> 2) + nl4];
#pragma unroll
    for (int i = 0; i < 4; i++) {
        int k = kl + i * 16;
        float4 v = ((const float4*)rhs)[(size_t)(k0 + k) * (NN / 4) + (n0 >> 2) + nl4];
        tileT[nl4 * 4 + 0][k] = __float2half_rn(qclip(v.x, s4.x));
        tileT[nl4 * 4 + 1][k] = __float2half_rn(qclip(v.y, s4.y));
        tileT[nl4 * 4 + 2][k] = __float2half_rn(qclip(v.z, s4.z));
        tileT[nl4 * 4 + 3][k] = __float2half_rn(qclip(v.w, s4.w));
    }
    __syncthreads();
#pragma unroll
    for (int i = 0; i < 2; i++) {
        int idx = i * 256 + t;
        int n = idx >> 3, s8 = idx & 7;
        uint4 u = *(uint4*)&tileT[n][s8 * 8];
        *(uint4*)&g_qBT[(size_t)(n0 + n) * KK + k0 + s8 * 8] = u;
    }
}

// ---------------------------------------------------------------------------
// Kernel 4: pipelined fp16 GEMM with ldmatrix fragment loads (R5 config)
// Block 256x128, 16 warps (4m x 4n), warp tile 64x32, 4-stage cp.async.
// ---------------------------------------------------------------------------
__device__ __forceinline__ void mma_f16(float& c0, float& c1, float& c2, float& c3,
                                        uint32_t a0, uint32_t a1, uint32_t a2, uint32_t a3,
                                        uint32_t b0, uint32_t b1) {
    asm volatile(
        "mma.sync.aligned.m16n8k16.row.col.f32.f16.f16.f32 "
        "{%0,%1,%2,%3}, {%4,%5,%6,%7}, {%8,%9}, {%0,%1,%2,%3};\n"
        : "+f"(c0), "+f"(c1), "+f"(c2), "+f"(c3)
        : "r"(a0), "r"(a1), "r"(a2), "r"(a3), "r"(b0), "r"(b1));
}

__device__ __forceinline__ void ldsm4(uint32_t& r0, uint32_t& r1, uint32_t& r2, uint32_t& r3,
                                      uint32_t addr) {
    asm volatile("ldmatrix.sync.aligned.m8n8.x4.shared.b16 {%0,%1,%2,%3}, [%4];"
                 : "=r"(r0), "=r"(r1), "=r"(r2), "=r"(r3) : "r"(addr));
}

__device__ __forceinline__ void cp16(uint32_t smem, const void* g) {
    asm volatile("cp.async.cg.shared.global [%0], [%1], 16;" :: "r"(smem), "l"(g));
}

__global__ void __launch_bounds__(512, 1)
gemm_f16_kernel(float* __restrict__ out) {
    extern __shared__ signed char sm[];
    uint32_t smb = (uint32_t)__cvta_generic_to_shared(sm);

    int tid = threadIdx.x;
    int warp = tid >> 5, lane = tid & 31;
    int wm = (warp & 3) * 64;    // warp m offset
    int wn = (warp >> 2) * 32;   // warp n offset
    int bm = blockIdx.y * BM, bn = blockIdx.x * BN;
    int grp = lane >> 2, tq = lane & 3;

    // cp.async mapping: A 4 chunks/thread, B 2 chunks/thread (16B each)
    const __half* gA[4];
    uint32_t sA[4];
#pragma unroll
    for (int p = 0; p < 4; p++) {
        int i = p * 512 + tid;
        int r = i >> 3, s = i & 7;
        gA[p] = g_qA + (size_t)(bm + r) * KK + s * 8;
        sA[p] = smb + r * RS + s * 16;
    }
    const __half* gB[2];
    uint32_t sB[2];
#pragma unroll
    for (int p = 0; p < 2; p++) {
        int i = p * 512 + tid;
        int r = i >> 3, s = i & 7;
        gB[p] = g_qBT + (size_t)(bn + r) * KK + s * 8;
        sB[p] = smb + A_STG + r * RS + s * 16;
    }

    // ldmatrix per-lane base addresses
    uint32_t aLd = smb + (wm + (lane & 15)) * RS + (lane >> 4) * 16;
    uint32_t bLd = smb + A_STG +
                   (wn + ((lane >> 4) & 1) * 8 + (lane & 7)) * RS + ((lane >> 3) & 1) * 16;

    float acc[4][4][4];
#pragma unroll
    for (int mi = 0; mi < 4; mi++)
#pragma unroll
        for (int ni = 0; ni < 4; ni++)
#pragma unroll
            for (int r = 0; r < 4; r++) acc[mi][ni][r] = 0.0f;

    // Prologue: stages 0..NST-2
#pragma unroll
    for (int st = 0; st < NST - 1; st++) {
#pragma unroll
        for (int p = 0; p < 4; p++) cp16(sA[p] + st * STG, gA[p] + st * BK);
#pragma unroll
        for (int p = 0; p < 2; p++) cp16(sB[p] + st * STG, gB[p] + st * BK);
        asm volatile("cp.async.commit_group;");
    }

    int stage = 0;
    for (int kt = 0; kt < NCHUNK; kt++) {
        asm volatile("cp.async.wait_group %0;" :: "n"(NST - 2));
        __syncthreads();

        if (kt + NST - 1 < NCHUNK) {
            int st = stage + (NST - 1) >= NST ? stage - 1 : stage + NST - 1;
            int ko = (kt + NST - 1) * BK;
#pragma unroll
            for (int p = 0; p < 4; p++) cp16(sA[p] + st * STG, gA[p] + ko);
#pragma unroll
            for (int p = 0; p < 2; p++) cp16(sB[p] + st * STG, gB[p] + ko);
        }
        asm volatile("cp.async.commit_group;");

        uint32_t stoff = stage * STG;
#pragma unroll
        for (int ks = 0; ks < 4; ks++) {   // four K=16 steps per 64-elem chunk
            uint32_t a[4][4], b[4][2];
#pragma unroll
            for (int mi = 0; mi < 4; mi++)
                ldsm4(a[mi][0], a[mi][1], a[mi][2], a[mi][3],
                      aLd + stoff + mi * 16 * RS + ks * 32);
#pragma unroll
            for (int np = 0; np < 2; np++)
                ldsm4(b[2 * np][0], b[2 * np][1], b[2 * np + 1][0], b[2 * np + 1][1],
                      bLd + stoff + np * 16 * RS + ks * 32);
#pragma unroll
            for (int mi = 0; mi < 4; mi++)
#pragma unroll
                for (int ni = 0; ni < 4; ni++)
                    mma_f16(acc[mi][ni][0], acc[mi][ni][1], acc[mi][ni][2], acc[mi][ni][3],
                            a[mi][0], a[mi][1], a[mi][2], a[mi][3], b[ni][0], b[ni][1]);
        }
        stage = (stage + 1 == NST) ? 0 : stage + 1;
    }

    // Epilogue: dequant + store
#pragma unroll
    for (int mi = 0; mi < 4; mi++) {
        int gm0 = bm + wm + mi * 16 + grp;
        float s0 = g_lsc[gm0];
        float s1 = g_lsc[gm0 + 8];
#pragma unroll
        for (int ni = 0; ni < 4; ni++) {
            int gn = bn + wn + ni * 8 + tq * 2;
            float r0 = g_rsc[gn];
            float r1 = g_rsc[gn + 1];
            float2 o0, o1;
            o0.x = acc[mi][ni][0] * s0 * r0;
            o0.y = acc[mi][ni][1] * s0 * r1;
            o1.x = acc[mi][ni][2] * s1 * r0;
            o1.y = acc[mi][ni][3] * s1 * r1;
            *(float2*)(out + (size_t)gm0 * NN + gn) = o0;
            *(float2*)(out + (size_t)(gm0 + 8) * NN + gn) = o1;
        }
    }
}

// ---------------------------------------------------------------------------
extern "C" void kernel_launch(void* const* d_in, const int* in_sizes, int n_in,
                              void* d_out, int out_size) {
    const float* lhs = (const float*)d_in[0];
    const float* rhs = (const float*)d_in[1];
    if (n_in >= 2 && in_sizes[0] == KK * NN && in_sizes[1] == MM * KK) {
        const float* t = lhs; lhs = rhs; rhs = t;
    }
    float* out = (float*)d_out;

    cudaFuncSetAttribute(gemm_f16_kernel, cudaFuncAttributeMaxDynamicSharedMemorySize, SMEM_REQ);

    quant_lhs_kernel<<<MM, 256>>>(lhs);
    rhs_pmax_kernel<<<dim3(NN / 1024, 32), 256>>>(rhs);
    rhs_scale_kernel<<<NN / 1024, 256>>>();
    quant_rhs_kernel<<<dim3(NN / 64, KK / 64), 256>>>(rhs);
    gemm_f16_kernel<<<dim3(NN / BN, MM / BM), 512, SMEM_REQ>>>(out);
}

// round 10
// speedup vs baseline: 1.1043x; 1.0540x over previous
#include <cuda_runtime.h>
#include <cuda_fp16.h>
#include <cstdint>

#define MM 8192
#define KK 4096
#define NN 4096

// GEMM tiling (fp16 mainloop) — R5 structure (best so far)
#define BM 256
#define BN 128
#define BK 64             // K elems per stage (128 bytes of fp16)
#define NST 4
#define NCHUNK (KK / BK)  // 64
#define RS 144            // smem row stride bytes (128B data + 16B pad)

#define A_STG (BM * RS)           // 36864
#define B_STG (BN * RS)           // 18432
#define STG (A_STG + B_STG)       // 55296
#define SMEM_REQ (NST * STG)      // 221184

// Scratch (device globals — no allocation allowed)
__device__ __half g_qA[(size_t)MM * KK];   // [M][K] fp16 (integer values)
__device__ __half g_qBT[(size_t)NN * KK];  // [N][K] fp16 (B transposed)
__device__ float g_lsc[MM];
__device__ float g_rsc[NN];
__device__ float g_pmax[32 * NN];

__device__ __forceinline__ float qclip(float v, float s) {
    return fminf(fmaxf(rintf(v / s), -127.0f), 127.0f);
}

// ---------------------------------------------------------------------------
// Kernel 1: per-row absmax + quantize of lhs -> fp16 integers (16B stores)
// ---------------------------------------------------------------------------
__global__ __launch_bounds__(256) void quant_lhs_kernel(const float* __restrict__ lhs) {
    int row = blockIdx.x;
    int t = threadIdx.x;
    const float4* src = (const float4*)(lhs + (size_t)row * KK);
    float4 v[4];
    v[0] = src[2 * t];
    v[1] = src[2 * t + 1];
    v[2] = src[512 + 2 * t];
    v[3] = src[512 + 2 * t + 1];
    float m = 0.0f;
#pragma unroll
    for (int i = 0; i < 4; i++)
        m = fmaxf(m, fmaxf(fmaxf(fabsf(v[i].x), fabsf(v[i].y)),
                           fmaxf(fabsf(v[i].z), fabsf(v[i].w))));
#pragma unroll
    for (int o = 16; o > 0; o >>= 1) m = fmaxf(m, __shfl_xor_sync(0xffffffffu, m, o));
    __shared__ float red[8];
    if ((t & 31) == 0) red[t >> 5] = m;
    __syncthreads();
    m = red[0];
#pragma unroll
    for (int i = 1; i < 8; i++) m = fmaxf(m, red[i]);

    float scale = m / 127.0f;
    if (scale == 0.0f) scale = 1.0f;
    if (t == 0) g_lsc[row] = scale;

    uint4* qdst = (uint4*)(g_qA + (size_t)row * KK);
#pragma unroll
    for (int g = 0; g < 2; g++) {
        float4 a = v[2 * g], b = v[2 * g + 1];
        __half2 h0 = __floats2half2_rn(qclip(a.x, scale), qclip(a.y, scale));
        __half2 h1 = __floats2half2_rn(qclip(a.z, scale), qclip(a.w, scale));
        __half2 h2 = __floats2half2_rn(qclip(b.x, scale), qclip(b.y, scale));
        __half2 h3 = __floats2half2_rn(qclip(b.z, scale), qclip(b.w, scale));
        uint4 u;
        u.x = *(uint32_t*)&h0; u.y = *(uint32_t*)&h1;
        u.z = *(uint32_t*)&h2; u.w = *(uint32_t*)&h3;
        qdst[g * 256 + t] = u;
    }
}

// ---------------------------------------------------------------------------
// Kernel 2a/2b: per-column absmax of rhs (float4 columns)
// ---------------------------------------------------------------------------
__global__ __launch_bounds__(256) void rhs_pmax_kernel(const float* __restrict__ rhs) {
    int n4 = blockIdx.x * 256 + threadIdx.x;
    int k0 = blockIdx.y * 128;
    const float4* p = (const float4*)rhs + (size_t)k0 * (NN / 4) + n4;
    float4 m = make_float4(0.f, 0.f, 0.f, 0.f);
#pragma unroll 8
    for (int k = 0; k < 128; k++) {
        float4 v = p[(size_t)k * (NN / 4)];
        m.x = fmaxf(m.x, fabsf(v.x));
        m.y = fmaxf(m.y, fabsf(v.y));
        m.z = fmaxf(m.z, fabsf(v.z));
        m.w = fmaxf(m.w, fabsf(v.w));
    }
    ((float4*)g_pmax)[blockIdx.y * (NN / 4) + n4] = m;
}

__global__ __launch_bounds__(256) void rhs_scale_kernel() {
    int n4 = blockIdx.x * 256 + threadIdx.x;
    float4 m = make_float4(0.f, 0.f, 0.f, 0.f);
#pragma unroll
    for (int i = 0; i < 32; i++) {
        float4 v = ((const float4*)g_pmax)[i * (NN / 4) + n4];
        m.x = fmaxf(m.x, v.x); m.y = fmaxf(m.y, v.y);
        m.z = fmaxf(m.z, v.z); m.w = fmaxf(m.w, v.w);
    }
    float4 s;
    s.x = m.x / 127.0f; if (s.x == 0.0f) s.x = 1.0f;
    s.y = m.y / 127.0f; if (s.y == 0.0f) s.y = 1.0f;
    s.z = m.z / 127.0f; if (s.z == 0.0f) s.z = 1.0f;
    s.w = m.w / 127.0f; if (s.w == 0.0f) s.w = 1.0f;
    ((float4*)g_rsc)[n4] = s;
}

// ---------------------------------------------------------------------------
// Kernel 3: quantize rhs + transpose into [N][K] fp16
// ---------------------------------------------------------------------------
__global__ __launch_bounds__(256) void quant_rhs_kernel(const float* __restrict__ rhs) {
    __shared__ __half tileT[64][72];
    int k0 = blockIdx.y * 64, n0 = blockIdx.x * 64;
    int t = threadIdx.x;
    int nl4 = t & 15;
    int kl = t >> 4;
    float4 s4 = ((const float4*)g_rsc)[(n0 >> 2) + nl4];
#pragma unroll
    for (int i = 0; i < 4; i++) {
        int k = kl + i * 16;
        float4 v = ((const float4*)rhs)[(size_t)(k0 + k) * (NN / 4) + (n0 >> 2) + nl4];
        tileT[nl4 * 4 + 0][k] = __float2half_rn(qclip(v.x, s4.x));
        tileT[nl4 * 4 + 1][k] = __float2half_rn(qclip(v.y, s4.y));
        tileT[nl4 * 4 + 2][k] = __float2half_rn(qclip(v.z, s4.z));
        tileT[nl4 * 4 + 3][k] = __float2half_rn(qclip(v.w, s4.w));
    }
    __syncthreads();
#pragma unroll
    for (int i = 0; i < 2; i++) {
        int idx = i * 256 + t;
        int n = idx >> 3, s8 = idx & 7;
        uint4 u = *(uint4*)&tileT[n][s8 * 8];
        *(uint4*)&g_qBT[(size_t)(n0 + n) * KK + k0 + s8 * 8] = u;
    }
}

// ---------------------------------------------------------------------------
// Kernel 4: pipelined fp16 GEMM — R5 structure + scheduled cp.async spreading
// and B-fragment register ping-pong.
// ---------------------------------------------------------------------------
__device__ __forceinline__ void mma_f16(float& c0, float& c1, float& c2, float& c3,
                                        uint32_t a0, uint32_t a1, uint32_t a2, uint32_t a3,
                                        uint32_t b0, uint32_t b1) {
    asm volatile(
        "mma.sync.aligned.m16n8k16.row.col.f32.f16.f16.f32 "
        "{%0,%1,%2,%3}, {%4,%5,%6,%7}, {%8,%9}, {%0,%1,%2,%3};\n"
        : "+f"(c0), "+f"(c1), "+f"(c2), "+f"(c3)
        : "r"(a0), "r"(a1), "r"(a2), "r"(a3), "r"(b0), "r"(b1));
}

__device__ __forceinline__ void ldsm4(uint32_t& r0, uint32_t& r1, uint32_t& r2, uint32_t& r3,
                                      uint32_t addr) {
    asm volatile("ldmatrix.sync.aligned.m8n8.x4.shared.b16 {%0,%1,%2,%3}, [%4];"
                 : "=r"(r0), "=r"(r1), "=r"(r2), "=r"(r3) : "r"(addr));
}

__device__ __forceinline__ void cp16(uint32_t smem, const void* g) {
    asm volatile("cp.async.cg.shared.global [%0], [%1], 16;" :: "r"(smem), "l"(g));
}

__global__ void __launch_bounds__(512, 1)
gemm_f16_kernel(float* __restrict__ out) {
    extern __shared__ signed char sm[];
    uint32_t smb = (uint32_t)__cvta_generic_to_shared(sm);

    int tid = threadIdx.x;
    int warp = tid >> 5, lane = tid & 31;
    int wm = (warp & 3) * 64;
    int wn = (warp >> 2) * 32;
    int bm = blockIdx.y * BM, bn = blockIdx.x * BN;
    int grp = lane >> 2, tq = lane & 3;

    // single-base cp.async addressing (offsets are compile-time per p)
    const __half* gAb = g_qA + (size_t)(bm + (tid >> 3)) * KK + (tid & 7) * 8;
    uint32_t sAb = smb + (tid >> 3) * RS + (tid & 7) * 16;
    const __half* gBb = g_qBT + (size_t)(bn + (tid >> 3)) * KK + (tid & 7) * 8;
    uint32_t sBb = smb + A_STG + (tid >> 3) * RS + (tid & 7) * 16;

    // ldmatrix per-lane base addresses
    uint32_t aLd = smb + (wm + (lane & 15)) * RS + (lane >> 4) * 16;
    uint32_t bLd = smb + A_STG +
                   (wn + ((lane >> 4) & 1) * 8 + (lane & 7)) * RS + ((lane >> 3) & 1) * 16;

    float acc[4][4][4];
#pragma unroll
    for (int mi = 0; mi < 4; mi++)
#pragma unroll
        for (int ni = 0; ni < 4; ni++)
#pragma unroll
            for (int r = 0; r < 4; r++) acc[mi][ni][r] = 0.0f;

    // Prologue: stages 0..NST-2
#pragma unroll
    for (int st = 0; st < NST - 1; st++) {
#pragma unroll
        for (int p = 0; p < 4; p++)
            cp16(sAb + st * STG + p * 64 * RS, gAb + st * BK + (size_t)p * 64 * KK);
#pragma unroll
        for (int p = 0; p < 2; p++)
            cp16(sBb + st * STG + p * 64 * RS, gBb + st * BK + (size_t)p * 64 * KK);
        asm volatile("cp.async.commit_group;");
    }

    int stage = 0;
    for (int kt = 0; kt < NCHUNK; kt++) {
        asm volatile("cp.async.wait_group %0;" :: "n"(NST - 2));
        __syncthreads();

        bool pf = (kt + NST - 1 < NCHUNK);
        int pst = (stage + NST - 1 >= NST) ? stage - 1 : stage + NST - 1;
        int ko = (kt + NST - 1) * BK;
        uint32_t stoff = stage * STG;

        uint32_t a[4][4], b[2][4][2];
        // B fragments for ks=0
#pragma unroll
        for (int np = 0; np < 2; np++)
            ldsm4(b[0][2 * np][0], b[0][2 * np][1], b[0][2 * np + 1][0], b[0][2 * np + 1][1],
                  bLd + stoff + np * 16 * RS);

#pragma unroll
        for (int ks = 0; ks < 4; ks++) {
            int cur = ks & 1;
#pragma unroll
            for (int mi = 0; mi < 4; mi++)
                ldsm4(a[mi][0], a[mi][1], a[mi][2], a[mi][3],
                      aLd + stoff + mi * 16 * RS + ks * 32);
            // prefetch next ks's B fragments
            if (ks < 3) {
#pragma unroll
                for (int np = 0; np < 2; np++)
                    ldsm4(b[cur ^ 1][2 * np][0], b[cur ^ 1][2 * np][1],
                          b[cur ^ 1][2 * np + 1][0], b[cur ^ 1][2 * np + 1][1],
                          bLd + stoff + np * 16 * RS + (ks + 1) * 32);
            }
            // spread next-stage cp.async issues: 2 per ks for ks=0..2
            if (pf) {
                if (ks == 0) {
                    cp16(sAb + pst * STG + 0 * 64 * RS, gAb + ko + (size_t)0 * 64 * KK);
                    cp16(sAb + pst * STG + 1 * 64 * RS, gAb + ko + (size_t)1 * 64 * KK);
                } else if (ks == 1) {
                    cp16(sAb + pst * STG + 2 * 64 * RS, gAb + ko + (size_t)2 * 64 * KK);
                    cp16(sAb + pst * STG + 3 * 64 * RS, gAb + ko + (size_t)3 * 64 * KK);
                } else if (ks == 2) {
                    cp16(sBb + pst * STG + 0 * 64 * RS, gBb + ko + (size_t)0 * 64 * KK);
                    cp16(sBb + pst * STG + 1 * 64 * RS, gBb + ko + (size_t)1 * 64 * KK);
                }
            }
#pragma unroll
            for (int mi = 0; mi < 4; mi++)
#pragma unroll
                for (int ni = 0; ni < 4; ni++)
                    mma_f16(acc[mi][ni][0], acc[mi][ni][1], acc[mi][ni][2], acc[mi][ni][3],
                            a[mi][0], a[mi][1], a[mi][2], a[mi][3],
                            b[cur][ni][0], b[cur][ni][1]);
        }
        asm volatile("cp.async.commit_group;");
        stage = (stage + 1 == NST) ? 0 : stage + 1;
    }

    // Epilogue: dequant + store
#pragma unroll
    for (int mi = 0; mi < 4; mi++) {
        int gm0 = bm + wm + mi * 16 + grp;
        float s0 = g_lsc[gm0];
        float s1 = g_lsc[gm0 + 8];
#pragma unroll
        for (int ni = 0; ni < 4; ni++) {
            int gn = bn + wn + ni * 8 + tq * 2;
            float r0 = g_rsc[gn];
            float r1 = g_rsc[gn + 1];
            float2 o0, o1;
            o0.x = acc[mi][ni][0] * s0 * r0;
            o0.y = acc[mi][ni][1] * s0 * r1;
            o1.x = acc[mi][ni][2] * s1 * r0;
            o1.y = acc[mi][ni][3] * s1 * r1;
            *(float2*)(out + (size_t)gm0 * NN + gn) = o0;
            *(float2*)(out + (size_t)(gm0 + 8) * NN + gn) = o1;
        }
    }
}

// ---------------------------------------------------------------------------
extern "C" void kernel_launch(void* const* d_in, const int* in_sizes, int n_in,
                              void* d_out, int out_size) {
    const float* lhs = (const float*)d_in[0];
    const float* rhs = (const float*)d_in[1];
    if (n_in >= 2 && in_sizes[0] == KK * NN && in_sizes[1] == MM * KK) {
        const float* t = lhs; lhs = rhs; rhs = t;
    }
    float* out = (float*)d_out;

    cudaFuncSetAttribute(gemm_f16_kernel, cudaFuncAttributeMaxDynamicSharedMemorySize, SMEM_REQ);

    quant_lhs_kernel<<<MM, 256>>>(lhs);
    rhs_pmax_kernel<<<dim3(NN / 1024, 32), 256>>>(rhs);
    rhs_scale_kernel<<<NN / 1024, 256>>>();
    quant_rhs_kernel<<<dim3(NN / 64, KK / 64), 256>>>(rhs);
    gemm_f16_kernel<<<dim3(NN / BN, MM / BM), 512, SMEM_REQ>>>(out);
}

// round 11
// speedup vs baseline: 1.1074x; 1.0028x over previous
#include <cuda_runtime.h>
#include <cuda_fp16.h>
#include <cstdint>

#define MM 8192
#define KK 4096
#define NN 4096

// GEMM tiling (fp16 mainloop) — R5 structure + R10 scheduling (best: 749.7us)
#define BM 256
#define BN 128
#define BK 64             // K elems per stage (128 bytes of fp16)
#define NST 4
#define NCHUNK (KK / BK)  // 64
#define RS 144            // smem row stride bytes (128B data + 16B pad)

#define A_STG (BM * RS)           // 36864
#define B_STG (BN * RS)           // 18432
#define STG (A_STG + B_STG)       // 55296
#define SMEM_REQ (NST * STG)      // 221184

// Scratch (device globals — no allocation allowed)
__device__ __half g_qA[(size_t)MM * KK];   // [M][K] fp16 (integer values)
__device__ __half g_qBT[(size_t)NN * KK];  // [N][K] fp16 (B transposed)
__device__ float g_lsc[MM];
__device__ float g_rsc[NN];
__device__ float g_pmax[32 * NN];

__device__ __forceinline__ float qclip(float v, float s) {
    return fminf(fmaxf(rintf(v / s), -127.0f), 127.0f);
}

// ---------------------------------------------------------------------------
// Kernel 1: per-row absmax + quantize of lhs -> fp16 integers (16B stores)
// ---------------------------------------------------------------------------
__global__ __launch_bounds__(256) void quant_lhs_kernel(const float* __restrict__ lhs) {
    int row = blockIdx.x;
    int t = threadIdx.x;
    const float4* src = (const float4*)(lhs + (size_t)row * KK);
    float4 v[4];
    v[0] = src[2 * t];
    v[1] = src[2 * t + 1];
    v[2] = src[512 + 2 * t];
    v[3] = src[512 + 2 * t + 1];
    float m = 0.0f;
#pragma unroll
    for (int i = 0; i < 4; i++)
        m = fmaxf(m, fmaxf(fmaxf(fabsf(v[i].x), fabsf(v[i].y)),
                           fmaxf(fabsf(v[i].z), fabsf(v[i].w))));
#pragma unroll
    for (int o = 16; o > 0; o >>= 1) m = fmaxf(m, __shfl_xor_sync(0xffffffffu, m, o));
    __shared__ float red[8];
    if ((t & 31) == 0) red[t >> 5] = m;
    __syncthreads();
    m = red[0];
#pragma unroll
    for (int i = 1; i < 8; i++) m = fmaxf(m, red[i]);

    float scale = m / 127.0f;
    if (scale == 0.0f) scale = 1.0f;
    if (t == 0) g_lsc[row] = scale;

    uint4* qdst = (uint4*)(g_qA + (size_t)row * KK);
#pragma unroll
    for (int g = 0; g < 2; g++) {
        float4 a = v[2 * g], b = v[2 * g + 1];
        __half2 h0 = __floats2half2_rn(qclip(a.x, scale), qclip(a.y, scale));
        __half2 h1 = __floats2half2_rn(qclip(a.z, scale), qclip(a.w, scale));
        __half2 h2 = __floats2half2_rn(qclip(b.x, scale), qclip(b.y, scale));
        __half2 h3 = __floats2half2_rn(qclip(b.z, scale), qclip(b.w, scale));
        uint4 u;
        u.x = *(uint32_t*)&h0; u.y = *(uint32_t*)&h1;
        u.z = *(uint32_t*)&h2; u.w = *(uint32_t*)&h3;
        qdst[g * 256 + t] = u;
    }
}

// ---------------------------------------------------------------------------
// Kernel 2a/2b: per-column absmax of rhs (float4 columns)
// ---------------------------------------------------------------------------
__global__ __launch_bounds__(256) void rhs_pmax_kernel(const float* __restrict__ rhs) {
    int n4 = blockIdx.x * 256 + threadIdx.x;
    int k0 = blockIdx.y * 128;
    const float4* p = (const float4*)rhs + (size_t)k0 * (NN / 4) + n4;
    float4 m = make_float4(0.f, 0.f, 0.f, 0.f);
#pragma unroll 8
    for (int k = 0; k < 128; k++) {
        float4 v = p[(size_t)k * (NN / 4)];
        m.x = fmaxf(m.x, fabsf(v.x));
        m.y = fmaxf(m.y, fabsf(v.y));
        m.z = fmaxf(m.z, fabsf(v.z));
        m.w = fmaxf(m.w, fabsf(v.w));
    }
    ((float4*)g_pmax)[blockIdx.y * (NN / 4) + n4] = m;
}

__global__ __launch_bounds__(256) void rhs_scale_kernel() {
    int n4 = blockIdx.x * 256 + threadIdx.x;
    float4 m = make_float4(0.f, 0.f, 0.f, 0.f);
#pragma unroll
    for (int i = 0; i < 32; i++) {
        float4 v = ((const float4*)g_pmax)[i * (NN / 4) + n4];
        m.x = fmaxf(m.x, v.x); m.y = fmaxf(m.y, v.y);
        m.z = fmaxf(m.z, v.z); m.w = fmaxf(m.w, v.w);
    }
    float4 s;
    s.x = m.x / 127.0f; if (s.x == 0.0f) s.x = 1.0f;
    s.y = m.y / 127.0f; if (s.y == 0.0f) s.y = 1.0f;
    s.z = m.z / 127.0f; if (s.z == 0.0f) s.z = 1.0f;
    s.w = m.w / 127.0f; if (s.w == 0.0f) s.w = 1.0f;
    ((float4*)g_rsc)[n4] = s;
}

// ---------------------------------------------------------------------------
// Kernel 3: quantize rhs + transpose into [N][K] fp16
// ---------------------------------------------------------------------------
__global__ __launch_bounds__(256) void quant_rhs_kernel(const float* __restrict__ rhs) {
    __shared__ __half tileT[64][72];
    int k0 = blockIdx.y * 64, n0 = blockIdx.x * 64;
    int t = threadIdx.x;
    int nl4 = t & 15;
    int kl = t >> 4;
    float4 s4 = ((const float4*)g_rsc)[(n0 >> 2) + nl4];
#pragma unroll
    for (int i = 0; i < 4; i++) {
        int k = kl + i * 16;
        float4 v = ((const float4*)rhs)[(size_t)(k0 + k) * (NN / 4) + (n0 >> 2) + nl4];
        tileT[nl4 * 4 + 0][k] = __float2half_rn(qclip(v.x, s4.x));
        tileT[nl4 * 4 + 1][k] = __float2half_rn(qclip(v.y, s4.y));
        tileT[nl4 * 4 + 2][k] = __float2half_rn(qclip(v.z, s4.z));
        tileT[nl4 * 4 + 3][k] = __float2half_rn(qclip(v.w, s4.w));
    }
    __syncthreads();
#pragma unroll
    for (int i = 0; i < 2; i++) {
        int idx = i * 256 + t;
        int n = idx >> 3, s8 = idx & 7;
        uint4 u = *(uint4*)&tileT[n][s8 * 8];
        *(uint4*)&g_qBT[(size_t)(n0 + n) * KK + k0 + s8 * 8] = u;
    }
}

// ---------------------------------------------------------------------------
// Kernel 4: pipelined fp16 GEMM — R10 scheduling + in-place A rotation
// ---------------------------------------------------------------------------
__device__ __forceinline__ void mma_f16(float& c0, float& c1, float& c2, float& c3,
                                        uint32_t a0, uint32_t a1, uint32_t a2, uint32_t a3,
                                        uint32_t b0, uint32_t b1) {
    asm volatile(
        "mma.sync.aligned.m16n8k16.row.col.f32.f16.f16.f32 "
        "{%0,%1,%2,%3}, {%4,%5,%6,%7}, {%8,%9}, {%0,%1,%2,%3};\n"
        : "+f"(c0), "+f"(c1), "+f"(c2), "+f"(c3)
        : "r"(a0), "r"(a1), "r"(a2), "r"(a3), "r"(b0), "r"(b1));
}

__device__ __forceinline__ void ldsm4(uint32_t& r0, uint32_t& r1, uint32_t& r2, uint32_t& r3,
                                      uint32_t addr) {
    asm volatile("ldmatrix.sync.aligned.m8n8.x4.shared.b16 {%0,%1,%2,%3}, [%4];"
                 : "=r"(r0), "=r"(r1), "=r"(r2), "=r"(r3) : "r"(addr));
}

__device__ __forceinline__ void cp16(uint32_t smem, const void* g) {
    asm volatile("cp.async.cg.shared.global [%0], [%1], 16;" :: "r"(smem), "l"(g));
}

__global__ void __launch_bounds__(512, 1)
gemm_f16_kernel(float* __restrict__ out) {
    extern __shared__ signed char sm[];
    uint32_t smb = (uint32_t)__cvta_generic_to_shared(sm);

    int tid = threadIdx.x;
    int warp = tid >> 5, lane = tid & 31;
    int wm = (warp & 3) * 64;
    int wn = (warp >> 2) * 32;
    int bm = blockIdx.y * BM, bn = blockIdx.x * BN;
    int grp = lane >> 2, tq = lane & 3;

    const __half* gAb = g_qA + (size_t)(bm + (tid >> 3)) * KK + (tid & 7) * 8;
    uint32_t sAb = smb + (tid >> 3) * RS + (tid & 7) * 16;
    const __half* gBb = g_qBT + (size_t)(bn + (tid >> 3)) * KK + (tid & 7) * 8;
    uint32_t sBb = smb + A_STG + (tid >> 3) * RS + (tid & 7) * 16;

    uint32_t aLd = smb + (wm + (lane & 15)) * RS + (lane >> 4) * 16;
    uint32_t bLd = smb + A_STG +
                   (wn + ((lane >> 4) & 1) * 8 + (lane & 7)) * RS + ((lane >> 3) & 1) * 16;

    float acc[4][4][4];
#pragma unroll
    for (int mi = 0; mi < 4; mi++)
#pragma unroll
        for (int ni = 0; ni < 4; ni++)
#pragma unroll
            for (int r = 0; r < 4; r++) acc[mi][ni][r] = 0.0f;

    // Prologue: stages 0..NST-2
#pragma unroll
    for (int st = 0; st < NST - 1; st++) {
#pragma unroll
        for (int p = 0; p < 4; p++)
            cp16(sAb + st * STG + p * 64 * RS, gAb + st * BK + (size_t)p * 64 * KK);
#pragma unroll
        for (int p = 0; p < 2; p++)
            cp16(sBb + st * STG + p * 64 * RS, gBb + st * BK + (size_t)p * 64 * KK);
        asm volatile("cp.async.commit_group;");
    }

    int stage = 0;
    for (int kt = 0; kt < NCHUNK; kt++) {
        asm volatile("cp.async.wait_group %0;" :: "n"(NST - 2));
        __syncthreads();

        bool pf = (kt + NST - 1 < NCHUNK);
        int pst = (stage + NST - 1 >= NST) ? stage - 1 : stage + NST - 1;
        int ko = (kt + NST - 1) * BK;
        uint32_t stoff = stage * STG;

        uint32_t a[4][4], b[2][4][2];
        // ks=0 fragments (cold loads right after barrier)
#pragma unroll
        for (int mi = 0; mi < 4; mi++)
            ldsm4(a[mi][0], a[mi][1], a[mi][2], a[mi][3],
                  aLd + stoff + mi * 16 * RS);
#pragma unroll
        for (int np = 0; np < 2; np++)
            ldsm4(b[0][2 * np][0], b[0][2 * np][1], b[0][2 * np + 1][0], b[0][2 * np + 1][1],
                  bLd + stoff + np * 16 * RS);

#pragma unroll
        for (int ks = 0; ks < 4; ks++) {
            int cur = ks & 1;
            // prefetch next ks's B fragments (ping-pong buffer)
            if (ks < 3) {
#pragma unroll
                for (int np = 0; np < 2; np++)
                    ldsm4(b[cur ^ 1][2 * np][0], b[cur ^ 1][2 * np][1],
                          b[cur ^ 1][2 * np + 1][0], b[cur ^ 1][2 * np + 1][1],
                          bLd + stoff + np * 16 * RS + (ks + 1) * 32);
            }
            // spread next-stage cp.async issues across ks steps
            if (pf) {
                if (ks == 0) {
                    cp16(sAb + pst * STG + 0 * 64 * RS, gAb + ko + (size_t)0 * 64 * KK);
                    cp16(sAb + pst * STG + 1 * 64 * RS, gAb + ko + (size_t)1 * 64 * KK);
                } else if (ks == 1) {
                    cp16(sAb + pst * STG + 2 * 64 * RS, gAb + ko + (size_t)2 * 64 * KK);
                    cp16(sAb + pst * STG + 3 * 64 * RS, gAb + ko + (size_t)3 * 64 * KK);
                } else if (ks == 2) {
                    cp16(sBb + pst * STG + 0 * 64 * RS, gBb + ko + (size_t)0 * 64 * KK);
                    cp16(sBb + pst * STG + 1 * 64 * RS, gBb + ko + (size_t)1 * 64 * KK);
                }
            }
            // MMAs; after mi's group, a[mi] is dead -> rotate in next ks's A in place
#pragma unroll
            for (int mi = 0; mi < 4; mi++) {
#pragma unroll
                for (int ni = 0; ni < 4; ni++)
                    mma_f16(acc[mi][ni][0], acc[mi][ni][1], acc[mi][ni][2], acc[mi][ni][3],
                            a[mi][0], a[mi][1], a[mi][2], a[mi][3],
                            b[cur][ni][0], b[cur][ni][1]);
                if (ks < 3)
                    ldsm4(a[mi][0], a[mi][1], a[mi][2], a[mi][3],
                          aLd + stoff + mi * 16 * RS + (ks + 1) * 32);
            }
        }
        asm volatile("cp.async.commit_group;");
        stage = (stage + 1 == NST) ? 0 : stage + 1;
    }

    // Epilogue: dequant + store
#pragma unroll
    for (int mi = 0; mi < 4; mi++) {
        int gm0 = bm + wm + mi * 16 + grp;
        float s0 = g_lsc[gm0];
        float s1 = g_lsc[gm0 + 8];
#pragma unroll
        for (int ni = 0; ni < 4; ni++) {
            int gn = bn + wn + ni * 8 + tq * 2;
            float r0 = g_rsc[gn];
            float r1 = g_rsc[gn + 1];
            float2 o0, o1;
            o0.x = acc[mi][ni][0] * s0 * r0;
            o0.y = acc[mi][ni][1] * s0 * r1;
            o1.x = acc[mi][ni][2] * s1 * r0;
            o1.y = acc[mi][ni][3] * s1 * r1;
            *(float2*)(out + (size_t)gm0 * NN + gn) = o0;
            *(float2*)(out + (size_t)(gm0 + 8) * NN + gn) = o1;
        }
    }
}

// ---------------------------------------------------------------------------
extern "C" void kernel_launch(void* const* d_in, const int* in_sizes, int n_in,
                              void* d_out, int out_size) {
    const float* lhs = (const float*)d_in[0];
    const float* rhs = (const float*)d_in[1];
    if (n_in >= 2 && in_sizes[0] == KK * NN && in_sizes[1] == MM * KK) {
        const float* t = lhs; lhs = rhs; rhs = t;
    }
    float* out = (float*)d_out;

    cudaFuncSetAttribute(gemm_f16_kernel, cudaFuncAttributeMaxDynamicSharedMemorySize, SMEM_REQ);

    quant_lhs_kernel<<<MM, 256>>>(lhs);
    rhs_pmax_kernel<<<dim3(NN / 1024, 32), 256>>>(rhs);
    rhs_scale_kernel<<<NN / 1024, 256>>>();
    quant_rhs_kernel<<<dim3(NN / 64, KK / 64), 256>>>(rhs);
    gemm_f16_kernel<<<dim3(NN / BN, MM / BM), 512, SMEM_REQ>>>(out);
}

// round 12
// speedup vs baseline: 1.1229x; 1.0139x over previous
#include <cuda_runtime.h>
#include <cuda_fp16.h>
#include <cstdint>

#define MM 8192
#define KK 4096
#define NN 4096

// GEMM tiling (fp16 mainloop) — R11 configuration (best: 747.6us)
#define BM 256
#define BN 128
#define BK 64             // K elems per stage (128 bytes of fp16)
#define NST 4
#define NCHUNK (KK / BK)  // 64
#define RS 144            // smem row stride bytes (128B data + 16B pad)

#define A_STG (BM * RS)           // 36864
#define B_STG (BN * RS)           // 18432
#define STG (A_STG + B_STG)       // 55296
#define SMEM_REQ (NST * STG)      // 221184

#define PMAX_BLOCKS 128           // 4 n-groups x 32 k-chunks

// Scratch (device globals — no allocation allowed)
__device__ __half g_qA[(size_t)MM * KK];   // [M][K] fp16 (integer values)
__device__ __half g_qBT[(size_t)NN * KK];  // [N][K] fp16 (B transposed)
__device__ float g_lsc[MM];
__device__ float g_rsc[NN];
__device__ float g_pmax[32 * NN];

__device__ __forceinline__ float qclip(float v, float s) {
    return fminf(fmaxf(rintf(v / s), -127.0f), 127.0f);
}

// ---------------------------------------------------------------------------
// Kernel 1 (fused): per-row absmax+quantize of lhs  AND  rhs column pmax.
// Blocks [0, PMAX_BLOCKS) do rhs pmax; blocks [PMAX_BLOCKS, +MM) do lhs rows.
// Both streams run concurrently -> higher aggregate HBM utilization.
// ---------------------------------------------------------------------------
__global__ __launch_bounds__(256) void fused_lhsq_pmax_kernel(
        const float* __restrict__ lhs, const float* __restrict__ rhs) {
    int t = threadIdx.x;
    if (blockIdx.x < PMAX_BLOCKS) {
        // ---- rhs pmax part ----
        int id = blockIdx.x;
        int bx = id & 3, by = id >> 2;          // bx: n-group, by: k-chunk
        int n4 = bx * 256 + t;                  // float4 index over N
        int k0 = by * 128;
        const float4* p = (const float4*)rhs + (size_t)k0 * (NN / 4) + n4;
        float4 m = make_float4(0.f, 0.f, 0.f, 0.f);
#pragma unroll 8
        for (int k = 0; k < 128; k++) {
            float4 v = __ldcs(p + (size_t)k * (NN / 4));
            m.x = fmaxf(m.x, fabsf(v.x));
            m.y = fmaxf(m.y, fabsf(v.y));
            m.z = fmaxf(m.z, fabsf(v.z));
            m.w = fmaxf(m.w, fabsf(v.w));
        }
        ((float4*)g_pmax)[by * (NN / 4) + n4] = m;
        return;
    }
    // ---- lhs quant part ----
    int row = blockIdx.x - PMAX_BLOCKS;
    const float4* src = (const float4*)(lhs + (size_t)row * KK);
    float4 v[4];
    v[0] = __ldcs(src + 2 * t);
    v[1] = __ldcs(src + 2 * t + 1);
    v[2] = __ldcs(src + 512 + 2 * t);
    v[3] = __ldcs(src + 512 + 2 * t + 1);
    float m = 0.0f;
#pragma unroll
    for (int i = 0; i < 4; i++)
        m = fmaxf(m, fmaxf(fmaxf(fabsf(v[i].x), fabsf(v[i].y)),
                           fmaxf(fabsf(v[i].z), fabsf(v[i].w))));
#pragma unroll
    for (int o = 16; o > 0; o >>= 1) m = fmaxf(m, __shfl_xor_sync(0xffffffffu, m, o));
    __shared__ float red[8];
    if ((t & 31) == 0) red[t >> 5] = m;
    __syncthreads();
    m = red[0];
#pragma unroll
    for (int i = 1; i < 8; i++) m = fmaxf(m, red[i]);

    float scale = m / 127.0f;
    if (scale == 0.0f) scale = 1.0f;
    if (t == 0) g_lsc[row] = scale;

    uint4* qdst = (uint4*)(g_qA + (size_t)row * KK);
#pragma unroll
    for (int g = 0; g < 2; g++) {
        float4 a = v[2 * g], b = v[2 * g + 1];
        __half2 h0 = __floats2half2_rn(qclip(a.x, scale), qclip(a.y, scale));
        __half2 h1 = __floats2half2_rn(qclip(a.z, scale), qclip(a.w, scale));
        __half2 h2 = __floats2half2_rn(qclip(b.x, scale), qclip(b.y, scale));
        __half2 h3 = __floats2half2_rn(qclip(b.z, scale), qclip(b.w, scale));
        uint4 u;
        u.x = *(uint32_t*)&h0; u.y = *(uint32_t*)&h1;
        u.z = *(uint32_t*)&h2; u.w = *(uint32_t*)&h3;
        qdst[g * 256 + t] = u;
    }
}

// ---------------------------------------------------------------------------
// Kernel 2: reduce pmax chunks -> per-column scales
// ---------------------------------------------------------------------------
__global__ __launch_bounds__(256) void rhs_scale_kernel() {
    int n4 = blockIdx.x * 256 + threadIdx.x;
    float4 m = make_float4(0.f, 0.f, 0.f, 0.f);
#pragma unroll
    for (int i = 0; i < 32; i++) {
        float4 v = ((const float4*)g_pmax)[i * (NN / 4) + n4];
        m.x = fmaxf(m.x, v.x); m.y = fmaxf(m.y, v.y);
        m.z = fmaxf(m.z, v.z); m.w = fmaxf(m.w, v.w);
    }
    float4 s;
    s.x = m.x / 127.0f; if (s.x == 0.0f) s.x = 1.0f;
    s.y = m.y / 127.0f; if (s.y == 0.0f) s.y = 1.0f;
    s.z = m.z / 127.0f; if (s.z == 0.0f) s.z = 1.0f;
    s.w = m.w / 127.0f; if (s.w == 0.0f) s.w = 1.0f;
    ((float4*)g_rsc)[n4] = s;
}

// ---------------------------------------------------------------------------
// Kernel 3: quantize rhs + transpose into [N][K] fp16
// ---------------------------------------------------------------------------
__global__ __launch_bounds__(256) void quant_rhs_kernel(const float* __restrict__ rhs) {
    __shared__ __half tileT[64][72];
    int k0 = blockIdx.y * 64, n0 = blockIdx.x * 64;
    int t = threadIdx.x;
    int nl4 = t & 15;
    int kl = t >> 4;
    float4 s4 = ((const float4*)g_rsc)[(n0 >> 2) + nl4];
#pragma unroll
    for (int i = 0; i < 4; i++) {
        int k = kl + i * 16;
        float4 v = __ldcs((const float4*)rhs + (size_t)(k0 + k) * (NN / 4) + (n0 >> 2) + nl4);
        tileT[nl4 * 4 + 0][k] = __float2half_rn(qclip(v.x, s4.x));
        tileT[nl4 * 4 + 1][k] = __float2half_rn(qclip(v.y, s4.y));
        tileT[nl4 * 4 + 2][k] = __float2half_rn(qclip(v.z, s4.z));
        tileT[nl4 * 4 + 3][k] = __float2half_rn(qclip(v.w, s4.w));
    }
    __syncthreads();
#pragma unroll
    for (int i = 0; i < 2; i++) {
        int idx = i * 256 + t;
        int n = idx >> 3, s8 = idx & 7;
        uint4 u = *(uint4*)&tileT[n][s8 * 8];
        *(uint4*)&g_qBT[(size_t)(n0 + n) * KK + k0 + s8 * 8] = u;
    }
}

// ---------------------------------------------------------------------------
// Kernel 4: pipelined fp16 GEMM — R11 (unchanged)
// ---------------------------------------------------------------------------
__device__ __forceinline__ void mma_f16(float& c0, float& c1, float& c2, float& c3,
                                        uint32_t a0, uint32_t a1, uint32_t a2, uint32_t a3,
                                        uint32_t b0, uint32_t b1) {
    asm volatile(
        "mma.sync.aligned.m16n8k16.row.col.f32.f16.f16.f32 "
        "{%0,%1,%2,%3}, {%4,%5,%6,%7}, {%8,%9}, {%0,%1,%2,%3};\n"
        : "+f"(c0), "+f"(c1), "+f"(c2), "+f"(c3)
        : "r"(a0), "r"(a1), "r"(a2), "r"(a3), "r"(b0), "r"(b1));
}

__device__ __forceinline__ void ldsm4(uint32_t& r0, uint32_t& r1, uint32_t& r2, uint32_t& r3,
                                      uint32_t addr) {
    asm volatile("ldmatrix.sync.aligned.m8n8.x4.shared.b16 {%0,%1,%2,%3}, [%4];"
                 : "=r"(r0), "=r"(r1), "=r"(r2), "=r"(r3) : "r"(addr));
}

__device__ __forceinline__ void cp16(uint32_t smem, const void* g) {
    asm volatile("cp.async.cg.shared.global [%0], [%1], 16;" :: "r"(smem), "l"(g));
}

__global__ void __launch_bounds__(512, 1)
gemm_f16_kernel(float* __restrict__ out) {
    extern __shared__ signed char sm[];
    uint32_t smb = (uint32_t)__cvta_generic_to_shared(sm);

    int tid = threadIdx.x;
    int warp = tid >> 5, lane = tid & 31;
    int wm = (warp & 3) * 64;
    int wn = (warp >> 2) * 32;
    int bm = blockIdx.y * BM, bn = blockIdx.x * BN;
    int grp = lane >> 2, tq = lane & 3;

    const __half* gAb = g_qA + (size_t)(bm + (tid >> 3)) * KK + (tid & 7) * 8;
    uint32_t sAb = smb + (tid >> 3) * RS + (tid & 7) * 16;
    const __half* gBb = g_qBT + (size_t)(bn + (tid >> 3)) * KK + (tid & 7) * 8;
    uint32_t sBb = smb + A_STG + (tid >> 3) * RS + (tid & 7) * 16;

    uint32_t aLd = smb + (wm + (lane & 15)) * RS + (lane >> 4) * 16;
    uint32_t bLd = smb + A_STG +
                   (wn + ((lane >> 4) & 1) * 8 + (lane & 7)) * RS + ((lane >> 3) & 1) * 16;

    float acc[4][4][4];
#pragma unroll
    for (int mi = 0; mi < 4; mi++)
#pragma unroll
        for (int ni = 0; ni < 4; ni++)
#pragma unroll
            for (int r = 0; r < 4; r++) acc[mi][ni][r] = 0.0f;

#pragma unroll
    for (int st = 0; st < NST - 1; st++) {
#pragma unroll
        for (int p = 0; p < 4; p++)
            cp16(sAb + st * STG + p * 64 * RS, gAb + st * BK + (size_t)p * 64 * KK);
#pragma unroll
        for (int p = 0; p < 2; p++)
            cp16(sBb + st * STG + p * 64 * RS, gBb + st * BK + (size_t)p * 64 * KK);
        asm volatile("cp.async.commit_group;");
    }

    int stage = 0;
    for (int kt = 0; kt < NCHUNK; kt++) {
        asm volatile("cp.async.wait_group %0;" :: "n"(NST - 2));
        __syncthreads();

        bool pf = (kt + NST - 1 < NCHUNK);
        int pst = (stage + NST - 1 >= NST) ? stage - 1 : stage + NST - 1;
        int ko = (kt + NST - 1) * BK;
        uint32_t stoff = stage * STG;

        uint32_t a[4][4], b[2][4][2];
#pragma unroll
        for (int mi = 0; mi < 4; mi++)
            ldsm4(a[mi][0], a[mi][1], a[mi][2], a[mi][3],
                  aLd + stoff + mi * 16 * RS);
#pragma unroll
        for (int np = 0; np < 2; np++)
            ldsm4(b[0][2 * np][0], b[0][2 * np][1], b[0][2 * np + 1][0], b[0][2 * np + 1][1],
                  bLd + stoff + np * 16 * RS);

#pragma unroll
        for (int ks = 0; ks < 4; ks++) {
            int cur = ks & 1;
            if (ks < 3) {
#pragma unroll
                for (int np = 0; np < 2; np++)
                    ldsm4(b[cur ^ 1][2 * np][0], b[cur ^ 1][2 * np][1],
                          b[cur ^ 1][2 * np + 1][0], b[cur ^ 1][2 * np + 1][1],
                          bLd + stoff + np * 16 * RS + (ks + 1) * 32);
            }
            if (pf) {
                if (ks == 0) {
                    cp16(sAb + pst * STG + 0 * 64 * RS, gAb + ko + (size_t)0 * 64 * KK);
                    cp16(sAb + pst * STG + 1 * 64 * RS, gAb + ko + (size_t)1 * 64 * KK);
                } else if (ks == 1) {
                    cp16(sAb + pst * STG + 2 * 64 * RS, gAb + ko + (size_t)2 * 64 * KK);
                    cp16(sAb + pst * STG + 3 * 64 * RS, gAb + ko + (size_t)3 * 64 * KK);
                } else if (ks == 2) {
                    cp16(sBb + pst * STG + 0 * 64 * RS, gBb + ko + (size_t)0 * 64 * KK);
                    cp16(sBb + pst * STG + 1 * 64 * RS, gBb + ko + (size_t)1 * 64 * KK);
                }
            }
#pragma unroll
            for (int mi = 0; mi < 4; mi++) {
#pragma unroll
                for (int ni = 0; ni < 4; ni++)
                    mma_f16(acc[mi][ni][0], acc[mi][ni][1], acc[mi][ni][2], acc[mi][ni][3],
                            a[mi][0], a[mi][1], a[mi][2], a[mi][3],
                            b[cur][ni][0], b[cur][ni][1]);
                if (ks < 3)
                    ldsm4(a[mi][0], a[mi][1], a[mi][2], a[mi][3],
                          aLd + stoff + mi * 16 * RS + (ks + 1) * 32);
            }
        }
        asm volatile("cp.async.commit_group;");
        stage = (stage + 1 == NST) ? 0 : stage + 1;
    }

#pragma unroll
    for (int mi = 0; mi < 4; mi++) {
        int gm0 = bm + wm + mi * 16 + grp;
        float s0 = g_lsc[gm0];
        float s1 = g_lsc[gm0 + 8];
#pragma unroll
        for (int ni = 0; ni < 4; ni++) {
            int gn = bn + wn + ni * 8 + tq * 2;
            float r0 = g_rsc[gn];
            float r1 = g_rsc[gn + 1];
            float2 o0, o1;
            o0.x = acc[mi][ni][0] * s0 * r0;
            o0.y = acc[mi][ni][1] * s0 * r1;
            o1.x = acc[mi][ni][2] * s1 * r0;
            o1.y = acc[mi][ni][3] * s1 * r1;
            *(float2*)(out + (size_t)gm0 * NN + gn) = o0;
            *(float2*)(out + (size_t)(gm0 + 8) * NN + gn) = o1;
        }
    }
}

// ---------------------------------------------------------------------------
extern "C" void kernel_launch(void* const* d_in, const int* in_sizes, int n_in,
                              void* d_out, int out_size) {
    const float* lhs = (const float*)d_in[0];
    const float* rhs = (const float*)d_in[1];
    if (n_in >= 2 && in_sizes[0] == KK * NN && in_sizes[1] == MM * KK) {
        const float* t = lhs; lhs = rhs; rhs = t;
    }
    float* out = (float*)d_out;

    cudaFuncSetAttribute(gemm_f16_kernel, cudaFuncAttributeMaxDynamicSharedMemorySize, SMEM_REQ);

    fused_lhsq_pmax_kernel<<<MM + PMAX_BLOCKS, 256>>>(lhs, rhs);
    rhs_scale_kernel<<<NN / 1024, 256>>>();
    quant_rhs_kernel<<<dim3(NN / 64, KK / 64), 256>>>(rhs);
    gemm_f16_kernel<<<dim3(NN / BN, MM / BM), 512, SMEM_REQ>>>(out);
}